// round 12
// baseline (speedup 1.0000x reference)
#include <cuda_runtime.h>
#include <cuda_fp16.h>

// Problem constants
#define B_     256
#define C_IN_  8
#define N_     4096
#define K_     9
#define S_     2
#define C_OUT_ 8

#define NB_    (N_ * B_)
#define NB2_   (NB_ / 2)

#define WPAIRS_PER_CK 4    // C_OUT/2 f32x2 pairs per (s,c,k)
#define WPAIRS_PER_S  (C_IN_ * K_ * WPAIRS_PER_CK)   // 288
#define W_ELEMS       (S_ * C_IN_ * K_ * C_OUT_)     // 1152 floats

// Main-kernel tiling: 8 n x 64 b per block (8 warps; warp = 1 n x 64 b)
#define NT  8
#define BT  64
#define SOUT_STRIDE (BT + 2)   // 66: even (float2-aligned), ≡2 mod 32

// Scratch (device global: allocation-free rule). x transposed + fp16:
// (c, n, b), b innermost, stored as half2 pairs over b.
__device__ __half2 g_xT2[C_IN_ * N_ * B_ / 2];   // 16.8 MB

__device__ __forceinline__ unsigned long long splat2(float v) {
    unsigned long long r;
    asm("mov.b64 %0, {%1, %1};" : "=l"(r) : "f"(v));
    return r;
}
__device__ __forceinline__ void fma2(unsigned long long& acc,
                                     unsigned long long a,
                                     unsigned long long b) {
    asm("fma.rn.f32x2 %0, %1, %2, %0;" : "+l"(acc) : "l"(a), "l"(b));
}
__device__ __forceinline__ void unpack2(unsigned long long v, float& lo, float& hi) {
    asm("mov.b64 {%0, %1}, %2;" : "=f"(lo), "=f"(hi) : "l"(v));
}

// ---------------------------------------------------------------------------
// K1: x (B, C_IN, N) f32 -> g_xT2 (C_IN, N, B) fp16. float4 loads, 16B stores.
// ---------------------------------------------------------------------------
__global__ __launch_bounds__(256) void transpose_x_kernel(const float* __restrict__ x)
{
    __shared__ float tile[128][33];
    const int c  = blockIdx.z;
    const int n0 = blockIdx.x * 128;
    const int b0 = blockIdx.y * 32;
    const int tx = threadIdx.x;      // 0..31
    const int ty = threadIdx.y;      // 0..7

    #pragma unroll
    for (int j = 0; j < 4; ++j) {
        const int b = ty + 8 * j;
        const float4 v = *reinterpret_cast<const float4*>(
            x + ((size_t)(b0 + b) * C_IN_ + c) * N_ + n0 + 4 * tx);
        tile[4 * tx + 0][b] = v.x;
        tile[4 * tx + 1][b] = v.y;
        tile[4 * tx + 2][b] = v.z;
        tile[4 * tx + 3][b] = v.w;
    }
    __syncthreads();

    const int tid = ty * 32 + tx;
    #pragma unroll
    for (int j = 0; j < 2; ++j) {
        const int g = j * 256 + tid;
        const int n = g >> 2;
        const int q = g & 3;
        __half2 h[4];
        #pragma unroll
        for (int m = 0; m < 4; ++m)
            h[m] = __floats2half2_rn(tile[n][8 * q + 2 * m],
                                     tile[n][8 * q + 2 * m + 1]);
        *reinterpret_cast<uint4*>(
            g_xT2 + ((size_t)c * N_ + n0 + n) * (B_ / 2) + (b0 + 8 * q) / 2) =
            *reinterpret_cast<const uint4*>(h);
    }
}

// ---------------------------------------------------------------------------
// K2: fused main compute + output transpose.
// 5 CTAs/SM (regs capped at 51) to break the 32-warp RF ceiling.
// Block = 8 warps, tile = 8 n x 64 b; warp w owns n = n0 + w, lane covers
// b-pair (b0+2*lane, b0+2*lane+1) via one half2 gather (1 wavefront).
// Weights f32 in smem, broadcast LDS.128; all accumulation f32.
// grid (N/8, B/64) = 2048 blocks.
// ---------------------------------------------------------------------------
__global__ __launch_bounds__(256, 5)
void lattice_main_kernel(const int*   __restrict__ nbr,
                         const int*   __restrict__ sub_ids,
                         const float* __restrict__ weight,
                         const float* __restrict__ bias,
                         float*       __restrict__ out)
{
    __shared__ __align__(16) unsigned long long sw[S_ * WPAIRS_PER_S]; // 4608 B
    __shared__ __align__(16) unsigned long long sb[S_ * WPAIRS_PER_CK];
    __shared__ float sout[C_OUT_][NT][SOUT_STRIDE];                     // 16.9 KB

    const int tid  = threadIdx.x;
    const int lane = tid & 31;
    const int wid  = tid >> 5;

    {   // weight layout (s,c,k,d) is d-innermost -> raw copy = packed f32x2
        float* swf = reinterpret_cast<float*>(sw);
        #pragma unroll
        for (int i = tid; i < W_ELEMS; i += 256) swf[i] = weight[i];
        float* sbf = reinterpret_cast<float*>(sb);
        if (tid < S_ * C_OUT_) sbf[tid] = bias[tid];
    }
    __syncthreads();

    const int n0 = blockIdx.x * NT;
    const int b0 = blockIdx.y * BT;
    const int n  = n0 + wid;
    const int s  = __ldg(&sub_ids[n]);   // uniform across warp

    // half2 base for the b-pair (b0 + 2*lane, b0 + 2*lane + 1)
    const __half2* xb = g_xT2 + (b0 >> 1) + lane;
    const int* nbr_n = nbr + n * K_;

    // accA: b = b0+2*lane ; accB: b = b0+2*lane+1. Pair j = d (2j, 2j+1).
    unsigned long long accA0 = sb[s * WPAIRS_PER_CK + 0];
    unsigned long long accA1 = sb[s * WPAIRS_PER_CK + 1];
    unsigned long long accA2 = sb[s * WPAIRS_PER_CK + 2];
    unsigned long long accA3 = sb[s * WPAIRS_PER_CK + 3];
    unsigned long long accB0 = accA0, accB1 = accA1;
    unsigned long long accB2 = accA2, accB3 = accA3;

    const unsigned long long* wrow = sw + s * WPAIRS_PER_S;

    #pragma unroll
    for (int k = 0; k < K_; ++k) {
        const int ro = __ldg(nbr_n + k) * (B_ >> 1);   // uniform, half2 units
        const __half2* xk = xb + ro;
        const unsigned long long* wk = wrow + k * WPAIRS_PER_CK;

        #pragma unroll
        for (int c = 0; c < C_IN_; ++c) {
            const __half2 xh = __ldg(xk);             // 128B line: 1 wavefront
            xk += NB2_;                                // pointer walk (reg diet)
            const float2 xf = __half22float2(xh);
            const unsigned long long x0 = splat2(xf.x);
            const unsigned long long x1 = splat2(xf.y);
            const ulonglong2 wa = *reinterpret_cast<const ulonglong2*>(wk);     // bcast
            const ulonglong2 wb = *reinterpret_cast<const ulonglong2*>(wk + 2); // bcast
            wk += K_ * WPAIRS_PER_CK;                  // pointer walk
            fma2(accA0, x0, wa.x);
            fma2(accA1, x0, wa.y);
            fma2(accA2, x0, wb.x);
            fma2(accA3, x0, wb.y);
            fma2(accB0, x1, wa.x);
            fma2(accB1, x1, wa.y);
            fma2(accB2, x1, wb.x);
            fma2(accB3, x1, wb.y);
        }
    }

    // Stage: float2 stores along b at (d, wid). 8B-aligned; conflict-free.
    {
        float aLo, aHi, bLo, bHi;
        #define STAGE(J)                                                            \
            do {                                                                    \
                unpack2(accA##J, aLo, aHi);                                         \
                unpack2(accB##J, bLo, bHi);                                         \
                *reinterpret_cast<float2*>(&sout[2*(J)    ][wid][2*lane]) =         \
                    make_float2(aLo, bLo);                                          \
                *reinterpret_cast<float2*>(&sout[2*(J) + 1][wid][2*lane]) =         \
                    make_float2(aHi, bHi);                                          \
            } while (0)
        STAGE(0); STAGE(1); STAGE(2); STAGE(3);
        #undef STAGE
    }
    __syncthreads();

    // Epilogue: warp w owns d = w. lane = (g, nn): g = quarter-warp, nn = n idx.
    // Iteration p: bl = 4p + g; quarter-warp stores 8 consecutive n (32B).
    {
        const int d  = wid;
        const int g  = lane >> 3;        // 0..3
        const int nn = lane & 7;
        #pragma unroll
        for (int p = 0; p < 16; ++p) {
            const int bl = 4 * p + g;
            const float v = sout[d][nn][bl];
            out[((size_t)(b0 + bl) * C_OUT_ + d) * N_ + n0 + nn] = v;
        }
    }
}

extern "C" void kernel_launch(void* const* d_in, const int* in_sizes, int n_in,
                              void* d_out, int out_size)
{
    const float* x       = (const float*)d_in[0];   // (B, C_IN, N) f32
    const int*   nbr     = (const int*)  d_in[1];   // (N, K) i32
    const int*   sub_ids = (const int*)  d_in[2];   // (N,) i32
    const float* weight  = (const float*)d_in[3];   // (S, C_IN, K, C_OUT) f32
    const float* bias    = (const float*)d_in[4];   // (S, C_OUT) f32
    float*       out     = (float*)d_out;           // (B, C_OUT, N) f32

    dim3 tgrid(N_ / 128, B_ / 32, C_IN_);
    dim3 tblk(32, 8);
    transpose_x_kernel<<<tgrid, tblk>>>(x);

    dim3 mgrid(N_ / NT, B_ / BT);
    lattice_main_kernel<<<mgrid, 256>>>(nbr, sub_ids, weight, bias, out);
}

// round 13
// speedup vs baseline: 1.4671x; 1.4671x over previous
#include <cuda_runtime.h>
#include <cuda_fp16.h>
#include <cstdint>

// Problem constants
#define B_     256
#define C_IN_  8
#define N_     4096
#define K_     9
#define S_     2
#define C_OUT_ 8

#define W_ELEMS (S_ * C_IN_ * K_ * C_OUT_)   // 1152 floats

// Main tiling: block = 16 n x 64 b, 8 warps. Warp-item = (n, 16-b tile).
#define NT  16
#define BT  64

// Scratch: x as fp16 in (n, b, c) layout — c innermost (8 halves = 16B per (n,b)).
__device__ __half g_xh[N_ * B_ * C_IN_];   // 16.8 MB

// ---------------------------------------------------------------------------
// K1: x (B, C_IN, N) f32 -> g_xh (N, B, C_IN) fp16.
// Block: 32 n x 32 b x 8 c. Smem tile float[(c*32+b)*33 + n]:
//   phase-1 stores lanes-on-n (stride 1: conflict-free),
//   phase-2 reads banks = (33*(32c+b) + n) mod 32 = (b + n) mod 32: lanes=b -> distinct.
// grid (N/32, B/32) = 1024 blocks.
// ---------------------------------------------------------------------------
__global__ __launch_bounds__(256) void transpose_x_kernel(const float* __restrict__ x)
{
    __shared__ float tf[256 * 33];   // 33.8 KB
    const int tid = threadIdx.x;
    const int l   = tid & 31;
    const int w   = tid >> 5;
    const int n0  = blockIdx.x * 32;
    const int b0  = blockIdx.y * 32;

    // Phase 1: 256 (b,c) rows; warp w handles rows w*32 .. w*32+31.
    #pragma unroll
    for (int r = 0; r < 32; ++r) {
        const int row = w * 32 + r;          // bc index
        const int b = row >> 3;
        const int c = row & 7;
        const float v = x[((size_t)(b0 + b) * C_IN_ + c) * N_ + n0 + l];
        tf[(c * 32 + b) * 33 + l] = v;
    }
    __syncthreads();

    // Phase 2: per iteration warp w handles n = w + 8i, lanes = b.
    #pragma unroll
    for (int i = 0; i < 4; ++i) {
        const int n = w + 8 * i;
        __half2 h01 = __floats2half2_rn(tf[(0 * 32 + l) * 33 + n],
                                        tf[(1 * 32 + l) * 33 + n]);
        __half2 h23 = __floats2half2_rn(tf[(2 * 32 + l) * 33 + n],
                                        tf[(3 * 32 + l) * 33 + n]);
        __half2 h45 = __floats2half2_rn(tf[(4 * 32 + l) * 33 + n],
                                        tf[(5 * 32 + l) * 33 + n]);
        __half2 h67 = __floats2half2_rn(tf[(6 * 32 + l) * 33 + n],
                                        tf[(7 * 32 + l) * 33 + n]);
        uint4 val;
        val.x = *reinterpret_cast<uint32_t*>(&h01);
        val.y = *reinterpret_cast<uint32_t*>(&h23);
        val.z = *reinterpret_cast<uint32_t*>(&h45);
        val.w = *reinterpret_cast<uint32_t*>(&h67);
        *reinterpret_cast<uint4*>(
            &g_xh[((size_t)(n0 + n) * B_ + b0 + l) * C_IN_]) = val;
    }
}

// ---------------------------------------------------------------------------
// K2: tensor-core main kernel.
// Per item (n, 16-b tile): D(16b x 8d) = A(16b x 80ck) x B(80ck x 8d) via
// 5x mma.sync.m16n8k16 (fp16 in, f32 accum), K = ck ordered col = k*8 + c,
// padded k=9 (zero B halves). A fragments loaded directly from g_xh —
// each of the 4 frag regs per MMA is one 128B coalesced line.
// B fragments: 20 regs/thread (both s), built once from smem weights.
// Staging smem bank-bijective: SIDX d-stride 1092 (==4 mod 32), r-stride 17.
// grid (N/16, B/64) = 1024 blocks, 4 CTAs/SM.
// ---------------------------------------------------------------------------
#define SIDX(d, r, nl) ((d) * 1092 + (r) * 17 + (nl))

__global__ __launch_bounds__(256, 4)
void lattice_main_kernel(const int*   __restrict__ nbr,
                         const int*   __restrict__ sub_ids,
                         const float* __restrict__ weight,
                         const float* __restrict__ bias,
                         float*       __restrict__ out)
{
    __shared__ float sw[W_ELEMS];        // 4.6 KB
    __shared__ float sout[8 * 1092];     // 34.9 KB
    __shared__ int   snbr[NT][10];       // k padded to 10
    __shared__ int   ssub[NT];
    __shared__ float sbias[S_ * C_OUT_];

    const int tid = threadIdx.x;
    const int l   = tid & 31;
    const int w   = tid >> 5;
    const int g   = l >> 2;     // groupID (fragment row / d for B)
    const int t   = l & 3;      // thread-in-group

    const int n0 = blockIdx.x * NT;
    const int b0 = blockIdx.y * BT;

    // Prologue: weights + metadata to smem.
    #pragma unroll
    for (int i = tid; i < W_ELEMS; i += 256) sw[i] = weight[i];
    if (tid < NT * 10) {
        const int nl = tid / 10, kk = tid % 10;
        snbr[nl][kk] = nbr[(n0 + nl) * K_ + (kk < K_ ? kk : K_ - 1)];
    } else if (tid < NT * 10 + NT) {
        ssub[tid - NT * 10] = sub_ids[n0 + (tid - NT * 10)];
    } else if (tid < NT * 10 + NT + S_ * C_OUT_) {
        sbias[tid - NT * 10 - NT] = bias[tid - NT * 10 - NT];
    }
    __syncthreads();

    // Build B fragments (fp16) for both s, all 5 K-chunks.
    // b0 reg = {W[s][c=2t][k=2q][d=g], W[s][c=2t+1][k=2q][d=g]}
    // b1 reg = same with k=2q+1 (zero for q=4: k=9 pad).
    uint32_t bf0[S_][5], bf1[S_][5];
    #pragma unroll
    for (int s = 0; s < S_; ++s) {
        #pragma unroll
        for (int q = 0; q < 5; ++q) {
            const int base0 = ((s * C_IN_ + 2 * t)     * K_ + 2 * q) * C_OUT_ + g;
            const int base1 = ((s * C_IN_ + 2 * t + 1) * K_ + 2 * q) * C_OUT_ + g;
            __half2 h0 = __floats2half2_rn(sw[base0], sw[base1]);
            bf0[s][q] = *reinterpret_cast<uint32_t*>(&h0);
            if (q < 4) {
                __half2 h1 = __floats2half2_rn(sw[base0 + C_OUT_], sw[base1 + C_OUT_]);
                bf1[s][q] = *reinterpret_cast<uint32_t*>(&h1);
            } else {
                bf1[s][q] = 0u;
            }
        }
    }

    // Main: 8 items per warp. item = w*8 + it -> nl = item>>2, bt = item&3.
    #pragma unroll 1
    for (int it = 0; it < 8; ++it) {
        const int item = w * 8 + it;
        const int nl = item >> 2;
        const int bt = item & 3;
        const int s  = ssub[nl];                 // warp-uniform
        const int* nbrn = snbr[nl];

        float c0 = sbias[s * C_OUT_ + 2 * t];
        float c1 = sbias[s * C_OUT_ + 2 * t + 1];
        float c2 = c0, c3 = c1;

        // half-index offset within an n-plane: (b0 + bt*16 + g)*8 + 2t
        const size_t rowoff = (size_t)(b0 + bt * 16 + g) * C_IN_ + 2 * t;

        #pragma unroll
        for (int q = 0; q < 5; ++q) {
            const size_t p0 = (size_t)nbrn[2 * q]     * (B_ * C_IN_) + rowoff;
            const size_t p1 = (size_t)nbrn[2 * q + 1] * (B_ * C_IN_) + rowoff;
            const uint32_t a0 = __ldg(reinterpret_cast<const uint32_t*>(g_xh + p0));
            const uint32_t a1 = __ldg(reinterpret_cast<const uint32_t*>(g_xh + p0 + 64));
            const uint32_t a2 = __ldg(reinterpret_cast<const uint32_t*>(g_xh + p1));
            const uint32_t a3 = __ldg(reinterpret_cast<const uint32_t*>(g_xh + p1 + 64));
            const uint32_t B0 = s ? bf0[1][q] : bf0[0][q];
            const uint32_t B1 = s ? bf1[1][q] : bf1[0][q];
            asm volatile(
                "mma.sync.aligned.m16n8k16.row.col.f32.f16.f16.f32 "
                "{%0,%1,%2,%3}, {%4,%5,%6,%7}, {%8,%9}, {%0,%1,%2,%3};"
                : "+f"(c0), "+f"(c1), "+f"(c2), "+f"(c3)
                : "r"(a0), "r"(a1), "r"(a2), "r"(a3), "r"(B0), "r"(B1));
        }

        // Stage D: rows r=bt*16+g (c0,c1) and r+8 (c2,c3); cols d=2t, 2t+1.
        // Banks (4d + 17r + nl): bijective over the warp -> conflict-free.
        const int r = bt * 16 + g;
        sout[SIDX(2 * t,     r,     nl)] = c0;
        sout[SIDX(2 * t + 1, r,     nl)] = c1;
        sout[SIDX(2 * t,     r + 8, nl)] = c2;
        sout[SIDX(2 * t + 1, r + 8, nl)] = c3;
    }
    __syncthreads();

    // Epilogue: 512 (b,d) rows x 16 n. Warp w owns rows [w*64, w*64+64);
    // half-warps cover row pairs; 16 lanes = 16 consecutive n (64B line).
    {
        const int h  = l >> 4;
        const int nl = l & 15;
        #pragma unroll
        for (int p = 0; p < 32; ++p) {
            const int r512 = w * 64 + 2 * p + h;   // = b*8 + d
            const int b = r512 >> 3;
            const int d = r512 & 7;
            const float v = sout[SIDX(d, b, nl)];
            out[((size_t)(b0 + b) * C_OUT_ + d) * N_ + n0 + nl] = v;
        }
    }
}

extern "C" void kernel_launch(void* const* d_in, const int* in_sizes, int n_in,
                              void* d_out, int out_size)
{
    const float* x       = (const float*)d_in[0];   // (B, C_IN, N) f32
    const int*   nbr     = (const int*)  d_in[1];   // (N, K) i32
    const int*   sub_ids = (const int*)  d_in[2];   // (N,) i32
    const float* weight  = (const float*)d_in[3];   // (S, C_IN, K, C_OUT) f32
    const float* bias    = (const float*)d_in[4];   // (S, C_OUT) f32
    float*       out     = (float*)d_out;           // (B, C_OUT, N) f32

    dim3 tgrid(N_ / 32, B_ / 32);
    transpose_x_kernel<<<tgrid, 256>>>(x);

    dim3 mgrid(N_ / NT, B_ / BT);
    lattice_main_kernel<<<mgrid, 256>>>(nbr, sub_ids, weight, bias, out);
}